// round 3
// baseline (speedup 1.0000x reference)
#include <cuda_runtime.h>
#include <math.h>

#define NB   2
#define NT   2048
#define NMEL 100
#define ND   1024
#define NH   16
#define NDH  64
#define NWIN 512
#define NFF  4096
#define NCD  1024
#define NLAYER 6
#define LNEPS 1e-5f

// ---------------- scratch (device globals; no runtime allocation allowed) ----------------
__device__ float g_h   [NB*NT*ND];
__device__ float g_hn  [NB*NT*ND];
__device__ float g_qkv [NB*NT*3*ND];
__device__ float g_attn[NB*NT*ND];
__device__ float g_ff  [NB*NT*NFF];
__device__ float g_ta  [NB*NCD];
__device__ float g_tb  [NB*NCD];
__device__ float g_cond[NB*ND];
__device__ float g_ss  [NB*2*ND];
__device__ float g_rc  [NT*(NDH/2)];
__device__ float g_rs  [NT*(NDH/2)];

// ---------------- timestep embedding features ----------------
__global__ void k_tfeat(const float* __restrict__ t, float* __restrict__ out){
    int i = blockIdx.x*blockDim.x + threadIdx.x;
    if (i >= NB*NCD) return;
    int b = i / NCD, j = i % NCD;
    const int half = NCD/2;
    int idx = (j < half) ? j : (j - half);
    float f   = expf(-9.210340371976184f * (float)idx / (float)half); // ln(10000)
    float ang = t[b] * f;
    out[i] = (j < half) ? sinf(ang) : cosf(ang);
}

// ---------------- tiny GEMM: Y[b,n] = act(X[b,:] @ W + bias), B rows only ----------------
__global__ void k_sgemm(const float* __restrict__ X, const float* __restrict__ W,
                        const float* __restrict__ bias, float* __restrict__ Y,
                        int K, int N, int act){
    int i = blockIdx.x*blockDim.x + threadIdx.x;
    if (i >= NB*N) return;
    int b = i / N, n = i % N;
    const float* x = X + (size_t)b*K;
    float acc = 0.f;
    #pragma unroll 4
    for (int k = 0; k < K; k++) acc += x[k]*W[(size_t)k*N + n];
    acc += bias[n];
    if (act == 1) acc = acc / (1.f + expf(-acc));   // silu
    Y[i] = acc;
}

// ---------------- rope cos/sin tables ----------------
__global__ void k_rope_tab(){
    int i = blockIdx.x*blockDim.x + threadIdx.x;
    if (i >= NT*(NDH/2)) return;
    int t = i >> 5, j = i & 31;
    float freq = (float)pow(10000.0, -(double)(2*j) / (double)NDH);
    float ang  = (float)t * freq;
    g_rc[i] = cosf(ang);
    g_rs[i] = sinf(ang);
}

// ---------------- rope apply (in-place on q and k slots of qkv) ----------------
__global__ void k_rope(float* __restrict__ qkv){
    int i = blockIdx.x*blockDim.x + threadIdx.x;   // exactly 2^22 threads
    int j = i & 31;
    int h = (i >> 5) & 15;
    int c = (i >> 9) & 1;          // 0 = q, 1 = k
    int t = (i >> 10) & (NT-1);
    int b = i >> 21;
    size_t base = (((size_t)(b*NT + t)*3 + c)*NH + h) * NDH;
    float x1 = qkv[base + 2*j], x2 = qkv[base + 2*j + 1];
    float cs = g_rc[t*32 + j], sn = g_rs[t*32 + j];
    qkv[base + 2*j]     = x1*cs - x2*sn;
    qkv[base + 2*j + 1] = x1*sn + x2*cs;
}

// ---------------- LayerNorm (+ optional adaLN scale/shift) ----------------
__global__ __launch_bounds__(256) void k_ln(const float* __restrict__ X,
                                            const float* __restrict__ ss,
                                            float* __restrict__ Y){
    int row = blockIdx.x;              // b*NT + t
    int b = row / NT;
    const float4* x4 = (const float4*)(X + (size_t)row*ND);
    int tid = threadIdx.x;
    float4 v = x4[tid];
    float s = v.x+v.y+v.z+v.w;
    float q = v.x*v.x+v.y*v.y+v.z*v.z+v.w*v.w;
    #pragma unroll
    for (int o=16;o;o>>=1){ s += __shfl_xor_sync(0xffffffffu,s,o); q += __shfl_xor_sync(0xffffffffu,q,o); }
    __shared__ float shs[8], shq[8];
    __shared__ float smean, srstd;
    int w = tid>>5;
    if ((tid&31)==0){ shs[w]=s; shq[w]=q; }
    __syncthreads();
    if (tid==0){
        float S=0.f,Q=0.f;
        #pragma unroll
        for (int k=0;k<8;k++){ S+=shs[k]; Q+=shq[k]; }
        float mean = S*(1.f/ND);
        float var  = Q*(1.f/ND) - mean*mean;   // population variance (jnp.var)
        smean = mean; srstd = rsqrtf(var + LNEPS);
    }
    __syncthreads();
    float mean = smean, r = srstd;
    int n0 = tid*4;
    float4 o;
    o.x=(v.x-mean)*r; o.y=(v.y-mean)*r; o.z=(v.z-mean)*r; o.w=(v.w-mean)*r;
    if (ss){
        const float* sc = ss + (size_t)b*2*ND;
        const float* sh = sc + ND;
        o.x = o.x*(1.f+sc[n0  ]) + sh[n0  ];
        o.y = o.y*(1.f+sc[n0+1]) + sh[n0+1];
        o.z = o.z*(1.f+sc[n0+2]) + sh[n0+2];
        o.w = o.w*(1.f+sc[n0+3]) + sh[n0+3];
    }
    ((float4*)(Y + (size_t)row*ND))[tid] = o;
}

// ---------------- main tiled SGEMM: C = act(A@W + bias) (+resid) ----------------
// BM=128, BN=64, BK=16, 256 threads, 8x4 micro-tile.
__global__ __launch_bounds__(256) void k_gemm(const float* __restrict__ A, const float* __restrict__ W,
                                              const float* __restrict__ bias, const float* __restrict__ resid,
                                              float* __restrict__ C, int M, int N, int K, int act){
    __shared__ float As[16*132];   // As[k][m], padded
    __shared__ float Bs[16*68];    // Bs[k][n], padded
    int tid = threadIdx.x;
    int ty = tid >> 4, tx = tid & 15;
    int m0 = blockIdx.y * 128, n0 = blockIdx.x * 64;
    float acc[8][4];
    #pragma unroll
    for (int i=0;i<8;i++)
        #pragma unroll
        for (int j=0;j<4;j++) acc[i][j]=0.f;

    for (int k0 = 0; k0 < K; k0 += 16){
        // ---- load A tile (128 x 16), store transposed ----
        #pragma unroll
        for (int rep=0; rep<2; rep++){
            int f = tid + rep*256;
            int r = f >> 2, c4 = (f & 3)*4;
            float x0=0.f,x1=0.f,x2=0.f,x3=0.f;
            int kc = k0 + c4;
            if (kc + 3 < K){
                float4 v = *(const float4*)(A + (size_t)(m0+r)*K + kc);
                x0=v.x;x1=v.y;x2=v.z;x3=v.w;
            } else if (kc < K){
                const float* ap = A + (size_t)(m0+r)*K + kc;
                x0 = ap[0];
                if (kc+1 < K) x1 = ap[1];
                if (kc+2 < K) x2 = ap[2];
            }
            As[(c4+0)*132 + r] = x0;
            As[(c4+1)*132 + r] = x1;
            As[(c4+2)*132 + r] = x2;
            As[(c4+3)*132 + r] = x3;
        }
        // ---- load W tile (16 x 64) ----
        {
            int r = tid >> 4, c4 = (tid & 15)*4;
            float x0=0.f,x1=0.f,x2=0.f,x3=0.f;
            int kr = k0 + r, nc = n0 + c4;
            if (kr < K){
                const float* wp = W + (size_t)kr*N + nc;
                if (nc + 3 < N){
                    float4 v = *(const float4*)wp;
                    x0=v.x;x1=v.y;x2=v.z;x3=v.w;
                } else {
                    if (nc   < N) x0 = wp[0];
                    if (nc+1 < N) x1 = wp[1];
                    if (nc+2 < N) x2 = wp[2];
                }
            }
            float4 sv; sv.x=x0; sv.y=x1; sv.z=x2; sv.w=x3;
            *(float4*)(Bs + r*68 + c4) = sv;
        }
        __syncthreads();
        #pragma unroll
        for (int kk=0; kk<16; kk++){
            float a[8], bv[4];
            #pragma unroll
            for (int i=0;i<8;i++) a[i] = As[kk*132 + ty + 16*i];
            #pragma unroll
            for (int j=0;j<4;j++) bv[j] = Bs[kk*68 + tx + 16*j];
            #pragma unroll
            for (int i=0;i<8;i++)
                #pragma unroll
                for (int j=0;j<4;j++)
                    acc[i][j] += a[i]*bv[j];
        }
        __syncthreads();
    }
    #pragma unroll
    for (int i=0;i<8;i++){
        int m = m0 + ty + 16*i;
        #pragma unroll
        for (int j=0;j<4;j++){
            int n = n0 + tx + 16*j;
            if (n < N){
                float v = acc[i][j] + bias[n];
                if (act == 1) v = 0.5f*v*(1.f + erff(v*0.70710678118654752f)); // exact gelu
                if (resid) v += resid[(size_t)m*N + n];
                C[(size_t)m*N + n] = v;
            }
        }
    }
}

// ---------------- flash-style windowed causal attention ----------------
// grid = (T/64, H, B), 256 threads, dyn smem = (2*64*65 + 64*64)*4 = 49664 B
__global__ __launch_bounds__(256) void k_attn(const float* __restrict__ qkv, float* __restrict__ O){
    extern __shared__ float sm[];
    float* Qs = sm;              // [64][65]   q-rows x dims (scaled)
    float* KP = sm + 64*65;      // [64][65]   K tile, reused as P tile
    float* Vs = sm + 2*64*65;    // [64][64]   V tile
    int qt = blockIdx.x, h = blockIdx.y, b = blockIdx.z;
    int tid = threadIdx.x, ty = tid>>4, tx = tid&15;
    int q0 = qt*64;
    const float scale = 0.125f;  // 1/sqrt(64)

    #pragma unroll
    for (int rep=0;rep<4;rep++){
        int f = tid + rep*256;
        int r = f>>4, c4 = (f&15)*4;
        size_t g = (((size_t)(b*NT + q0 + r)*3 + 0)*NH + h)*NDH + c4;
        float4 v = *(const float4*)(qkv + g);
        Qs[r*65 + c4  ] = v.x*scale;
        Qs[r*65 + c4+1] = v.y*scale;
        Qs[r*65 + c4+2] = v.z*scale;
        Qs[r*65 + c4+3] = v.w*scale;
    }
    __syncthreads();

    float Oa[4][4];
    float mo[4], lo[4];
    #pragma unroll
    for (int a=0;a<4;a++){
        mo[a] = -1e30f; lo[a] = 0.f;
        #pragma unroll
        for (int c=0;c<4;c++) Oa[a][c]=0.f;
    }

    int ktiles = min(8, qt+1);
    for (int jt=0; jt<ktiles; jt++){
        int j0 = jt*64;
        #pragma unroll
        for (int rep=0;rep<4;rep++){
            int f = tid + rep*256;
            int r = f>>4, c4 = (f&15)*4;
            int tok = NT - NWIN + j0 + r;
            size_t gk = (((size_t)(b*NT + tok)*3 + 1)*NH + h)*NDH + c4;
            float4 kv = *(const float4*)(qkv + gk);
            float4 vv = *(const float4*)(qkv + gk + (size_t)NH*NDH);
            KP[r*65+c4  ]=kv.x; KP[r*65+c4+1]=kv.y;
            KP[r*65+c4+2]=kv.z; KP[r*65+c4+3]=kv.w;
            *(float4*)(Vs + r*64 + c4) = vv;
        }
        __syncthreads();

        float S[4][4];
        #pragma unroll
        for (int a=0;a<4;a++)
            #pragma unroll
            for (int bb=0;bb<4;bb++) S[a][bb]=0.f;
        for (int d=0; d<64; d++){
            float qa[4], kb[4];
            #pragma unroll
            for (int a=0;a<4;a++)  qa[a] = Qs[(ty+16*a)*65 + d];
            #pragma unroll
            for (int bb=0;bb<4;bb++) kb[bb] = KP[(tx+16*bb)*65 + d];
            #pragma unroll
            for (int a=0;a<4;a++)
                #pragma unroll
                for (int bb=0;bb<4;bb++) S[a][bb] += qa[a]*kb[bb];
        }
        if (jt == qt){   // diagonal tile: mask j > q (only reachable for qt<8)
            #pragma unroll
            for (int a=0;a<4;a++)
                #pragma unroll
                for (int bb=0;bb<4;bb++)
                    if (tx+16*bb > ty+16*a) S[a][bb] = -1e30f;
        }

        float P[4][4];
        #pragma unroll
        for (int a=0;a<4;a++){
            float mx = fmaxf(fmaxf(S[a][0],S[a][1]), fmaxf(S[a][2],S[a][3]));
            mx = fmaxf(mx, __shfl_xor_sync(0xffffffffu, mx, 8));
            mx = fmaxf(mx, __shfl_xor_sync(0xffffffffu, mx, 4));
            mx = fmaxf(mx, __shfl_xor_sync(0xffffffffu, mx, 2));
            mx = fmaxf(mx, __shfl_xor_sync(0xffffffffu, mx, 1));
            float mn = fmaxf(mo[a], mx);
            float ls = 0.f;
            #pragma unroll
            for (int bb=0;bb<4;bb++){ P[a][bb] = expf(S[a][bb]-mn); ls += P[a][bb]; }
            ls += __shfl_xor_sync(0xffffffffu, ls, 8);
            ls += __shfl_xor_sync(0xffffffffu, ls, 4);
            ls += __shfl_xor_sync(0xffffffffu, ls, 2);
            ls += __shfl_xor_sync(0xffffffffu, ls, 1);
            float alpha = expf(mo[a]-mn);
            lo[a] = lo[a]*alpha + ls;
            mo[a] = mn;
            #pragma unroll
            for (int c=0;c<4;c++) Oa[a][c] *= alpha;
        }
        __syncthreads();                 // everyone done reading K
        #pragma unroll
        for (int a=0;a<4;a++)
            #pragma unroll
            for (int bb=0;bb<4;bb++)
                KP[(ty+16*a)*65 + tx+16*bb] = P[a][bb];
        __syncthreads();
        for (int jj=0;jj<64;jj++){
            float pa[4], vc[4];
            #pragma unroll
            for (int a=0;a<4;a++) pa[a] = KP[(ty+16*a)*65 + jj];
            #pragma unroll
            for (int c=0;c<4;c++) vc[c] = Vs[jj*64 + tx+16*c];
            #pragma unroll
            for (int a=0;a<4;a++)
                #pragma unroll
                for (int c=0;c<4;c++) Oa[a][c] += pa[a]*vc[c];
        }
        __syncthreads();
    }
    #pragma unroll
    for (int a=0;a<4;a++){
        int qq = q0 + ty + 16*a;
        float inv = 1.f/lo[a];
        #pragma unroll
        for (int c=0;c<4;c++)
            O[(((size_t)(b*NT+qq))*NH + h)*NDH + tx + 16*c] = Oa[a][c]*inv;
    }
}

// ---------------- orchestration ----------------
extern "C" void kernel_launch(void* const* d_in, const int* in_sizes, int n_in,
                              void* d_out, int out_size){
    (void)in_sizes; (void)n_in; (void)out_size;
    const float* x      = (const float*)d_in[0];
    const float* t      = (const float*)d_in[1];
    const float* W_in   = (const float*)d_in[2];
    const float* b_in   = (const float*)d_in[3];
    const float* Wt1    = (const float*)d_in[4];
    const float* bt1    = (const float*)d_in[5];
    const float* Wt2    = (const float*)d_in[6];
    const float* bt2    = (const float*)d_in[7];
    const float* Wcm    = (const float*)d_in[8];
    const float* bcm    = (const float*)d_in[9];
    const float* ada1_W = (const float*)d_in[10];
    const float* ada1_b = (const float*)d_in[11];
    const float* qkv_W  = (const float*)d_in[12];
    const float* qkv_b  = (const float*)d_in[13];
    const float* attno_W= (const float*)d_in[14];
    const float* attno_b= (const float*)d_in[15];
    const float* ada2_W = (const float*)d_in[16];
    const float* ada2_b = (const float*)d_in[17];
    const float* mlp_W1 = (const float*)d_in[18];
    const float* mlp_b1 = (const float*)d_in[19];
    const float* mlp_W2 = (const float*)d_in[20];
    const float* mlp_b2 = (const float*)d_in[21];
    const float* W_out  = (const float*)d_in[22];
    const float* b_out  = (const float*)d_in[23];

    float *p_h,*p_hn,*p_qkv,*p_attn,*p_ff,*p_ta,*p_tb,*p_cond,*p_ss;
    cudaGetSymbolAddress((void**)&p_h,    g_h);
    cudaGetSymbolAddress((void**)&p_hn,   g_hn);
    cudaGetSymbolAddress((void**)&p_qkv,  g_qkv);
    cudaGetSymbolAddress((void**)&p_attn, g_attn);
    cudaGetSymbolAddress((void**)&p_ff,   g_ff);
    cudaGetSymbolAddress((void**)&p_ta,   g_ta);
    cudaGetSymbolAddress((void**)&p_tb,   g_tb);
    cudaGetSymbolAddress((void**)&p_cond, g_cond);
    cudaGetSymbolAddress((void**)&p_ss,   g_ss);

    cudaFuncSetAttribute(k_attn, cudaFuncAttributeMaxDynamicSharedMemorySize, 49664);

    const int M = NB*NT;           // 4096

    // timestep conditioning
    k_tfeat<<<(NB*NCD+255)/256,256>>>(t, p_ta);
    k_sgemm<<<(NB*NCD+255)/256,256>>>(p_ta, Wt1, bt1, p_tb, NCD, NCD, 1);
    k_sgemm<<<(NB*NCD+255)/256,256>>>(p_tb, Wt2, bt2, p_ta, NCD, NCD, 0);
    k_sgemm<<<(NB*ND +255)/256,256>>>(p_ta, Wcm, bcm, p_cond, NCD, ND, 1);
    k_rope_tab<<<(NT*32+255)/256,256>>>();

    // input projection: h = x @ W_in + b_in   (K = 100)
    k_gemm<<<dim3(ND/64, M/128), 256>>>(x, W_in, b_in, nullptr, p_h, M, ND, NMEL, 0);

    for (int l = 0; l < NLAYER; l++){
        // adaLN 1
        k_sgemm<<<(NB*2*ND+255)/256,256>>>(p_cond, ada1_W + (size_t)l*ND*2*ND,
                                           ada1_b + (size_t)l*2*ND, p_ss, ND, 2*ND, 0);
        k_ln<<<M,256>>>(p_h, p_ss, p_hn);
        // qkv
        k_gemm<<<dim3(3*ND/64, M/128), 256>>>(p_hn, qkv_W + (size_t)l*ND*3*ND,
                                              qkv_b + (size_t)l*3*ND, nullptr, p_qkv,
                                              M, 3*ND, ND, 0);
        k_rope<<<(1<<22)/256,256>>>(p_qkv);
        k_attn<<<dim3(NT/64, NH, NB), 256, 49664>>>(p_qkv, p_attn);
        // attn out + residual
        k_gemm<<<dim3(ND/64, M/128), 256>>>(p_attn, attno_W + (size_t)l*ND*ND,
                                            attno_b + (size_t)l*ND, p_h, p_h,
                                            M, ND, ND, 0);
        // adaLN 2
        k_sgemm<<<(NB*2*ND+255)/256,256>>>(p_cond, ada2_W + (size_t)l*ND*2*ND,
                                           ada2_b + (size_t)l*2*ND, p_ss, ND, 2*ND, 0);
        k_ln<<<M,256>>>(p_h, p_ss, p_hn);
        // MLP
        k_gemm<<<dim3(NFF/64, M/128), 256>>>(p_hn, mlp_W1 + (size_t)l*ND*NFF,
                                             mlp_b1 + (size_t)l*NFF, nullptr, p_ff,
                                             M, NFF, ND, 1);   // exact gelu
        k_gemm<<<dim3(ND/64, M/128), 256>>>(p_ff, mlp_W2 + (size_t)l*NFF*ND,
                                            mlp_b2 + (size_t)l*ND, p_h, p_h,
                                            M, ND, NFF, 0);
    }

    // final LN + output projection (N = 100)
    k_ln<<<M,256>>>(p_h, nullptr, p_hn);
    k_gemm<<<dim3((NMEL+63)/64, M/128), 256>>>(p_hn, W_out, b_out, nullptr,
                                               (float*)d_out, M, NMEL, ND, 0);
}

// round 5
// speedup vs baseline: 2.0425x; 2.0425x over previous
#include <cuda_runtime.h>
#include <cuda_bf16.h>
#include <math.h>
#include <stdint.h>

#define NB   2
#define NT   2048
#define NMEL 100
#define ND   1024
#define NH   16
#define NDH  64
#define NWIN 512
#define NFF  4096
#define NCD  1024
#define NLAYER 6
#define LNEPS 1e-5f

// ---------------- scratch (device globals; no runtime allocation allowed) ----------------
__device__ float g_h   [NB*NT*ND];
__device__ float g_hn  [NB*NT*ND];
__device__ float g_qkv [NB*NT*3*ND];
__device__ float g_attn[NB*NT*ND];
__device__ float g_ff  [NB*NT*NFF];
__device__ float g_ta  [NB*NCD];
__device__ float g_tb  [NB*NCD];
__device__ float g_cond[NB*ND];
__device__ float g_ss  [NB*2*ND];
__device__ float g_rc  [NT*(NDH/2)];
__device__ float g_rs  [NT*(NDH/2)];

// converted weights: [N][K] bf16, hi + lo split
__device__ __nv_bfloat16 c_in_hi  [ND*NMEL];
__device__ __nv_bfloat16 c_in_lo  [ND*NMEL];
__device__ __nv_bfloat16 c_qkv_hi [NLAYER*3*ND*ND];
__device__ __nv_bfloat16 c_qkv_lo [NLAYER*3*ND*ND];
__device__ __nv_bfloat16 c_ao_hi  [NLAYER*ND*ND];
__device__ __nv_bfloat16 c_ao_lo  [NLAYER*ND*ND];
__device__ __nv_bfloat16 c_m1_hi  [NLAYER*NFF*ND];
__device__ __nv_bfloat16 c_m1_lo  [NLAYER*NFF*ND];
__device__ __nv_bfloat16 c_m2_hi  [NLAYER*ND*NFF];
__device__ __nv_bfloat16 c_m2_lo  [NLAYER*ND*NFF];
__device__ __nv_bfloat16 c_out_hi [NMEL*ND];
__device__ __nv_bfloat16 c_out_lo [NMEL*ND];

// ---------------- helpers ----------------
__device__ __forceinline__ uint32_t smem_u32(const void* p){
    uint32_t a;
    asm("{ .reg .u64 t; cvta.to.shared.u64 t, %1; cvt.u32.u64 %0, t; }" : "=r"(a) : "l"(p));
    return a;
}
#define LDSM4(d0,d1,d2,d3,addr) \
    asm volatile("ldmatrix.sync.aligned.m8n8.x4.shared.b16 {%0,%1,%2,%3}, [%4];" \
        : "=r"(d0),"=r"(d1),"=r"(d2),"=r"(d3) : "r"(addr))
#define MMA16816(c, a, b0, b1) \
    asm volatile("mma.sync.aligned.m16n8k16.row.col.f32.bf16.bf16.f32 " \
        "{%0,%1,%2,%3},{%4,%5,%6,%7},{%8,%9},{%0,%1,%2,%3};" \
        : "+f"((c)[0]),"+f"((c)[1]),"+f"((c)[2]),"+f"((c)[3]) \
        : "r"((a)[0]),"r"((a)[1]),"r"((a)[2]),"r"((a)[3]),"r"(b0),"r"(b1))

// ---------------- weight convert: W[K,N] fp32 -> [N,K] bf16 hi/lo ----------------
__global__ void k_wconv(const float* __restrict__ W, __nv_bfloat16* __restrict__ hi,
                        __nv_bfloat16* __restrict__ lo, int K, int N){
    __shared__ float t[32][33];
    int kb = blockIdx.y*32, nb = blockIdx.x*32;
    int x = threadIdx.x, y = threadIdx.y;   // 32 x 8
    #pragma unroll
    for (int i = 0; i < 32; i += 8){
        int k = kb + y + i, n = nb + x;
        t[y+i][x] = (k < K && n < N) ? W[(size_t)k*N + n] : 0.f;
    }
    __syncthreads();
    #pragma unroll
    for (int i = 0; i < 32; i += 8){
        int n = nb + y + i, k = kb + x;
        if (n < N && k < K){
            float v = t[x][y+i];
            __nv_bfloat16 h = __float2bfloat16_rn(v);
            float r = v - __bfloat162float(h);
            hi[(size_t)n*K + k] = h;
            lo[(size_t)n*K + k] = __float2bfloat16_rn(r);
        }
    }
}

// ---------------- tensor-core GEMM via mma.sync (bf16 hi/lo split, fp32 accum) ----------
// C[M,N] = act(A[M,K] @ Wt^T + bias) (+resid).  Wt = [N][K] bf16 hi/lo.
// CTA tile 128x128, 8 warps, warp tile 64x32 (4x4 of m16n8), BK=32.
#define SASTRIDE 40
__global__ __launch_bounds__(256, 2) void k_mgemm(
    const float* __restrict__ A,
    const __nv_bfloat16* __restrict__ Bhi, const __nv_bfloat16* __restrict__ Blo,
    const float* __restrict__ bias, const float* __restrict__ resid,
    float* __restrict__ C, int N, int K, int act)
{
    __shared__ __nv_bfloat16 sAh[128*SASTRIDE], sAl[128*SASTRIDE];
    __shared__ __nv_bfloat16 sBh[128*SASTRIDE], sBl[128*SASTRIDE];

    int tid = threadIdx.x, lane = tid & 31, w = tid >> 5;
    int m0 = blockIdx.y * 128, n0 = blockIdx.x * 128;
    int wm = (w & 1) * 64;      // warp m offset in tile
    int wn = (w >> 1) * 32;     // warp n offset in tile

    float acc[16][4];
    #pragma unroll
    for (int i = 0; i < 16; i++){
        acc[i][0]=0.f; acc[i][1]=0.f; acc[i][2]=0.f; acc[i][3]=0.f;
    }

    int nchunks = (K + 31) >> 5;
    for (int c = 0; c < nchunks; c++){
        int k0 = c * 32;
        __syncthreads();
        // ---- load A (128x32 f32 -> hi/lo bf16) and B (128x32 bf16 hi/lo) ----
        for (int i = tid; i < 2048; i += 256){
            int r = i >> 4, kk = (i & 15) * 2;
            int gk = k0 + kk;
            float2 v = make_float2(0.f, 0.f);
            if (gk < K) v = *(const float2*)(A + (size_t)(m0 + r)*K + gk);
            __nv_bfloat162 hh = __floats2bfloat162_rn(v.x, v.y);
            float2 hf = __bfloat1622float2(hh);
            __nv_bfloat162 ll = __floats2bfloat162_rn(v.x - hf.x, v.y - hf.y);
            *(uint32_t*)&sAh[r*SASTRIDE + kk] = *(uint32_t*)&hh;
            *(uint32_t*)&sAl[r*SASTRIDE + kk] = *(uint32_t*)&ll;

            int gn = n0 + r;
            uint32_t hp = 0u, lp = 0u;
            if (gn < N && gk < K){
                size_t e = (size_t)gn*K + gk;
                hp = *(const uint32_t*)(Bhi + e);
                lp = *(const uint32_t*)(Blo + e);
            }
            *(uint32_t*)&sBh[r*SASTRIDE + kk] = hp;
            *(uint32_t*)&sBl[r*SASTRIDE + kk] = lp;
        }
        __syncthreads();
        // ---- compute: 2 k16 steps ----
        #pragma unroll
        for (int ks = 0; ks < 2; ks++){
            int kb = ks * 16 + (lane >> 4) * 8;
            int rr = lane & 15;
            uint32_t ah[4][4], al[4][4], bfr[2][4];
            #pragma unroll
            for (int mi = 0; mi < 4; mi++){
                uint32_t ad = smem_u32(&sAh[(wm + mi*16 + rr)*SASTRIDE + kb]);
                LDSM4(ah[mi][0], ah[mi][1], ah[mi][2], ah[mi][3], ad);
            }
            #pragma unroll
            for (int mi = 0; mi < 4; mi++){
                uint32_t ad = smem_u32(&sAl[(wm + mi*16 + rr)*SASTRIDE + kb]);
                LDSM4(al[mi][0], al[mi][1], al[mi][2], al[mi][3], ad);
            }
            #pragma unroll
            for (int nj = 0; nj < 2; nj++){
                uint32_t ad = smem_u32(&sBh[(wn + nj*16 + rr)*SASTRIDE + kb]);
                LDSM4(bfr[nj][0], bfr[nj][1], bfr[nj][2], bfr[nj][3], ad);
            }
            #pragma unroll
            for (int mi = 0; mi < 4; mi++)
                #pragma unroll
                for (int ni = 0; ni < 4; ni++){
                    uint32_t b0 = bfr[ni>>1][(ni&1)];
                    uint32_t b1 = bfr[ni>>1][(ni&1)+2];
                    MMA16816(acc[mi*4+ni], ah[mi], b0, b1);   // hi*hi
                    MMA16816(acc[mi*4+ni], al[mi], b0, b1);   // lo*hi
                }
            #pragma unroll
            for (int nj = 0; nj < 2; nj++){
                uint32_t ad = smem_u32(&sBl[(wn + nj*16 + rr)*SASTRIDE + kb]);
                LDSM4(bfr[nj][0], bfr[nj][1], bfr[nj][2], bfr[nj][3], ad);
            }
            #pragma unroll
            for (int mi = 0; mi < 4; mi++)
                #pragma unroll
                for (int ni = 0; ni < 4; ni++){
                    uint32_t b0 = bfr[ni>>1][(ni&1)];
                    uint32_t b1 = bfr[ni>>1][(ni&1)+2];
                    MMA16816(acc[mi*4+ni], ah[mi], b0, b1);   // hi*lo
                }
        }
    }

    // ---- epilogue: bias (+gelu) (+resid), float2 stores ----
    #pragma unroll
    for (int mi = 0; mi < 4; mi++){
        #pragma unroll
        for (int ni = 0; ni < 4; ni++){
            float* ac = acc[mi*4+ni];
            int n = n0 + wn + ni*8 + (lane & 3)*2;
            if (n + 1 < N){
                float b0 = bias[n], b1 = bias[n+1];
                #pragma unroll
                for (int half = 0; half < 2; half++){
                    int m = m0 + wm + mi*16 + (lane >> 2) + half*8;
                    float v0 = ac[half*2]   + b0;
                    float v1 = ac[half*2+1] + b1;
                    if (act == 1){
                        v0 = 0.5f*v0*(1.f + erff(v0*0.70710678118654752f));
                        v1 = 0.5f*v1*(1.f + erff(v1*0.70710678118654752f));
                    }
                    if (resid){
                        float2 rp = *(const float2*)(resid + (size_t)m*N + n);
                        v0 += rp.x; v1 += rp.y;
                    }
                    float2 o = make_float2(v0, v1);
                    *(float2*)(C + (size_t)m*N + n) = o;
                }
            } else if (n < N){
                float b0 = bias[n];
                #pragma unroll
                for (int half = 0; half < 2; half++){
                    int m = m0 + wm + mi*16 + (lane >> 2) + half*8;
                    float v0 = ac[half*2] + b0;
                    if (act == 1) v0 = 0.5f*v0*(1.f + erff(v0*0.70710678118654752f));
                    if (resid) v0 += resid[(size_t)m*N + n];
                    C[(size_t)m*N + n] = v0;
                }
            }
        }
    }
}

// ---------------- timestep embedding features ----------------
__global__ void k_tfeat(const float* __restrict__ t, float* __restrict__ out){
    int i = blockIdx.x*blockDim.x + threadIdx.x;
    if (i >= NB*NCD) return;
    int b = i / NCD, j = i % NCD;
    const int half = NCD/2;
    int idx = (j < half) ? j : (j - half);
    float f   = expf(-9.210340371976184f * (float)idx / (float)half);
    float ang = t[b] * f;
    out[i] = (j < half) ? sinf(ang) : cosf(ang);
}

// ---------------- small GEMM (rows = NB only), k-split parallel ----------------
__global__ __launch_bounds__(256) void k_sgemm2(const float* __restrict__ X,
                                                const float* __restrict__ W,
                                                const float* __restrict__ bias,
                                                float* __restrict__ Y,
                                                int K, int N, int act){
    __shared__ float red[2][4][65];
    int lane = threadIdx.x & 63;
    int slice = threadIdx.x >> 6;
    int n = blockIdx.x*64 + lane;
    int kps = K >> 2;
    float a0 = 0.f, a1 = 0.f;
    if (n < N){
        const float* x0 = X;
        const float* x1 = X + K;
        int k0 = slice*kps, k1 = k0 + kps;
        #pragma unroll 4
        for (int k = k0; k < k1; k++){
            float w = W[(size_t)k*N + n];
            a0 += x0[k]*w; a1 += x1[k]*w;
        }
    }
    red[0][slice][lane] = a0;
    red[1][slice][lane] = a1;
    __syncthreads();
    if (threadIdx.x < 128){
        int bb = threadIdx.x >> 6, l = threadIdx.x & 63;
        float s = red[bb][0][l] + red[bb][1][l] + red[bb][2][l] + red[bb][3][l];
        int nn = blockIdx.x*64 + l;
        if (nn < N){
            s += bias[nn];
            if (act == 1) s = s / (1.f + expf(-s));
            Y[(size_t)bb*N + nn] = s;
        }
    }
}

// ---------------- rope tables + apply ----------------
__global__ void k_rope_tab(){
    int i = blockIdx.x*blockDim.x + threadIdx.x;
    if (i >= NT*(NDH/2)) return;
    int t = i >> 5, j = i & 31;
    float freq = (float)pow(10000.0, -(double)(2*j) / (double)NDH);
    float ang  = (float)t * freq;
    g_rc[i] = cosf(ang);
    g_rs[i] = sinf(ang);
}
__global__ void k_rope(float* __restrict__ qkv){
    int i = blockIdx.x*blockDim.x + threadIdx.x;
    int j = i & 31;
    int h = (i >> 5) & 15;
    int c = (i >> 9) & 1;
    int t = (i >> 10) & (NT-1);
    int b = i >> 21;
    size_t base = (((size_t)(b*NT + t)*3 + c)*NH + h) * NDH;
    float x1 = qkv[base + 2*j], x2 = qkv[base + 2*j + 1];
    float cs = g_rc[t*32 + j], sn = g_rs[t*32 + j];
    qkv[base + 2*j]     = x1*cs - x2*sn;
    qkv[base + 2*j + 1] = x1*sn + x2*cs;
}

// ---------------- LayerNorm (+ optional adaLN scale/shift) ----------------
__global__ __launch_bounds__(256) void k_ln(const float* __restrict__ X,
                                            const float* __restrict__ ss,
                                            float* __restrict__ Y){
    int row = blockIdx.x;
    int b = row / NT;
    const float4* x4 = (const float4*)(X + (size_t)row*ND);
    int tid = threadIdx.x;
    float4 v = x4[tid];
    float s = v.x+v.y+v.z+v.w;
    float q = v.x*v.x+v.y*v.y+v.z*v.z+v.w*v.w;
    #pragma unroll
    for (int o=16;o;o>>=1){ s += __shfl_xor_sync(0xffffffffu,s,o); q += __shfl_xor_sync(0xffffffffu,q,o); }
    __shared__ float shs[8], shq[8];
    __shared__ float smean, srstd;
    int w = tid>>5;
    if ((tid&31)==0){ shs[w]=s; shq[w]=q; }
    __syncthreads();
    if (tid==0){
        float S=0.f,Q=0.f;
        #pragma unroll
        for (int k=0;k<8;k++){ S+=shs[k]; Q+=shq[k]; }
        float mean = S*(1.f/ND);
        float var  = Q*(1.f/ND) - mean*mean;
        smean = mean; srstd = rsqrtf(var + LNEPS);
    }
    __syncthreads();
    float mean = smean, r = srstd;
    int n0 = tid*4;
    float4 o;
    o.x=(v.x-mean)*r; o.y=(v.y-mean)*r; o.z=(v.z-mean)*r; o.w=(v.w-mean)*r;
    if (ss){
        const float* sc = ss + (size_t)b*2*ND;
        const float* sh = sc + ND;
        o.x = o.x*(1.f+sc[n0  ]) + sh[n0  ];
        o.y = o.y*(1.f+sc[n0+1]) + sh[n0+1];
        o.z = o.z*(1.f+sc[n0+2]) + sh[n0+2];
        o.w = o.w*(1.f+sc[n0+3]) + sh[n0+3];
    }
    ((float4*)(Y + (size_t)row*ND))[tid] = o;
}

// ---------------- flash-style windowed causal attention (fp32) ----------------
__global__ __launch_bounds__(256) void k_attn(const float* __restrict__ qkv, float* __restrict__ O){
    extern __shared__ float sm[];
    float* Qs = sm;
    float* KP = sm + 64*65;
    float* Vs = sm + 2*64*65;
    int qt = blockIdx.x, h = blockIdx.y, b = blockIdx.z;
    int tid = threadIdx.x, ty = tid>>4, tx = tid&15;
    int q0 = qt*64;
    const float scale = 0.125f;

    #pragma unroll
    for (int rep=0;rep<4;rep++){
        int f = tid + rep*256;
        int r = f>>4, c4 = (f&15)*4;
        size_t g = (((size_t)(b*NT + q0 + r)*3 + 0)*NH + h)*NDH + c4;
        float4 v = *(const float4*)(qkv + g);
        Qs[r*65 + c4  ] = v.x*scale;
        Qs[r*65 + c4+1] = v.y*scale;
        Qs[r*65 + c4+2] = v.z*scale;
        Qs[r*65 + c4+3] = v.w*scale;
    }
    __syncthreads();

    float Oa[4][4];
    float mo[4], lo[4];
    #pragma unroll
    for (int a=0;a<4;a++){
        mo[a] = -1e30f; lo[a] = 0.f;
        #pragma unroll
        for (int c=0;c<4;c++) Oa[a][c]=0.f;
    }

    int ktiles = min(8, qt+1);
    for (int jt=0; jt<ktiles; jt++){
        int j0 = jt*64;
        #pragma unroll
        for (int rep=0;rep<4;rep++){
            int f = tid + rep*256;
            int r = f>>4, c4 = (f&15)*4;
            int tok = NT - NWIN + j0 + r;
            size_t gk = (((size_t)(b*NT + tok)*3 + 1)*NH + h)*NDH + c4;
            float4 kv = *(const float4*)(qkv + gk);
            float4 vv = *(const float4*)(qkv + gk + (size_t)NH*NDH);
            KP[r*65+c4  ]=kv.x; KP[r*65+c4+1]=kv.y;
            KP[r*65+c4+2]=kv.z; KP[r*65+c4+3]=kv.w;
            *(float4*)(Vs + r*64 + c4) = vv;
        }
        __syncthreads();

        float S[4][4];
        #pragma unroll
        for (int a=0;a<4;a++)
            #pragma unroll
            for (int bb=0;bb<4;bb++) S[a][bb]=0.f;
        for (int d=0; d<64; d++){
            float qa[4], kb[4];
            #pragma unroll
            for (int a=0;a<4;a++)  qa[a] = Qs[(ty+16*a)*65 + d];
            #pragma unroll
            for (int bb=0;bb<4;bb++) kb[bb] = KP[(tx+16*bb)*65 + d];
            #pragma unroll
            for (int a=0;a<4;a++)
                #pragma unroll
                for (int bb=0;bb<4;bb++) S[a][bb] += qa[a]*kb[bb];
        }
        if (jt == qt){
            #pragma unroll
            for (int a=0;a<4;a++)
                #pragma unroll
                for (int bb=0;bb<4;bb++)
                    if (tx+16*bb > ty+16*a) S[a][bb] = -1e30f;
        }

        float P[4][4];
        #pragma unroll
        for (int a=0;a<4;a++){
            float mx = fmaxf(fmaxf(S[a][0],S[a][1]), fmaxf(S[a][2],S[a][3]));
            mx = fmaxf(mx, __shfl_xor_sync(0xffffffffu, mx, 8));
            mx = fmaxf(mx, __shfl_xor_sync(0xffffffffu, mx, 4));
            mx = fmaxf(mx, __shfl_xor_sync(0xffffffffu, mx, 2));
            mx = fmaxf(mx, __shfl_xor_sync(0xffffffffu, mx, 1));
            float mn = fmaxf(mo[a], mx);
            float ls = 0.f;
            #pragma unroll
            for (int bb=0;bb<4;bb++){ P[a][bb] = expf(S[a][bb]-mn); ls += P[a][bb]; }
            ls += __shfl_xor_sync(0xffffffffu, ls, 8);
            ls += __shfl_xor_sync(0xffffffffu, ls, 4);
            ls += __shfl_xor_sync(0xffffffffu, ls, 2);
            ls += __shfl_xor_sync(0xffffffffu, ls, 1);
            float alpha = expf(mo[a]-mn);
            lo[a] = lo[a]*alpha + ls;
            mo[a] = mn;
            #pragma unroll
            for (int c=0;c<4;c++) Oa[a][c] *= alpha;
        }
        __syncthreads();
        #pragma unroll
        for (int a=0;a<4;a++)
            #pragma unroll
            for (int bb=0;bb<4;bb++)
                KP[(ty+16*a)*65 + tx+16*bb] = P[a][bb];
        __syncthreads();
        for (int jj=0;jj<64;jj++){
            float pa[4], vc[4];
            #pragma unroll
            for (int a=0;a<4;a++) pa[a] = KP[(ty+16*a)*65 + jj];
            #pragma unroll
            for (int c=0;c<4;c++) vc[c] = Vs[jj*64 + tx+16*c];
            #pragma unroll
            for (int a=0;a<4;a++)
                #pragma unroll
                for (int c=0;c<4;c++) Oa[a][c] += pa[a]*vc[c];
        }
        __syncthreads();
    }
    #pragma unroll
    for (int a=0;a<4;a++){
        int qq = q0 + ty + 16*a;
        float inv = 1.f/lo[a];
        #pragma unroll
        for (int c=0;c<4;c++)
            O[(((size_t)(b*NT+qq))*NH + h)*NDH + tx + 16*c] = Oa[a][c]*inv;
    }
}

// ---------------- orchestration ----------------
extern "C" void kernel_launch(void* const* d_in, const int* in_sizes, int n_in,
                              void* d_out, int out_size){
    (void)in_sizes; (void)n_in; (void)out_size;
    const float* x      = (const float*)d_in[0];
    const float* t      = (const float*)d_in[1];
    const float* W_in   = (const float*)d_in[2];
    const float* b_in   = (const float*)d_in[3];
    const float* Wt1    = (const float*)d_in[4];
    const float* bt1    = (const float*)d_in[5];
    const float* Wt2    = (const float*)d_in[6];
    const float* bt2    = (const float*)d_in[7];
    const float* Wcm    = (const float*)d_in[8];
    const float* bcm    = (const float*)d_in[9];
    const float* ada1_W = (const float*)d_in[10];
    const float* ada1_b = (const float*)d_in[11];
    const float* qkv_W  = (const float*)d_in[12];
    const float* qkv_b  = (const float*)d_in[13];
    const float* attno_W= (const float*)d_in[14];
    const float* attno_b= (const float*)d_in[15];
    const float* ada2_W = (const float*)d_in[16];
    const float* ada2_b = (const float*)d_in[17];
    const float* mlp_W1 = (const float*)d_in[18];
    const float* mlp_b1 = (const float*)d_in[19];
    const float* mlp_W2 = (const float*)d_in[20];
    const float* mlp_b2 = (const float*)d_in[21];
    const float* W_out  = (const float*)d_in[22];
    const float* b_out  = (const float*)d_in[23];

    float *p_h,*p_hn,*p_qkv,*p_attn,*p_ff,*p_ta,*p_tb,*p_cond,*p_ss;
    cudaGetSymbolAddress((void**)&p_h,    g_h);
    cudaGetSymbolAddress((void**)&p_hn,   g_hn);
    cudaGetSymbolAddress((void**)&p_qkv,  g_qkv);
    cudaGetSymbolAddress((void**)&p_attn, g_attn);
    cudaGetSymbolAddress((void**)&p_ff,   g_ff);
    cudaGetSymbolAddress((void**)&p_ta,   g_ta);
    cudaGetSymbolAddress((void**)&p_tb,   g_tb);
    cudaGetSymbolAddress((void**)&p_cond, g_cond);
    cudaGetSymbolAddress((void**)&p_ss,   g_ss);

    __nv_bfloat16 *w_in_h,*w_in_l,*w_qkv_h,*w_qkv_l,*w_ao_h,*w_ao_l;
    __nv_bfloat16 *w_m1_h,*w_m1_l,*w_m2_h,*w_m2_l,*w_out_h,*w_out_l;
    cudaGetSymbolAddress((void**)&w_in_h,  c_in_hi);
    cudaGetSymbolAddress((void**)&w_in_l,  c_in_lo);
    cudaGetSymbolAddress((void**)&w_qkv_h, c_qkv_hi);
    cudaGetSymbolAddress((void**)&w_qkv_l, c_qkv_lo);
    cudaGetSymbolAddress((void**)&w_ao_h,  c_ao_hi);
    cudaGetSymbolAddress((void**)&w_ao_l,  c_ao_lo);
    cudaGetSymbolAddress((void**)&w_m1_h,  c_m1_hi);
    cudaGetSymbolAddress((void**)&w_m1_l,  c_m1_lo);
    cudaGetSymbolAddress((void**)&w_m2_h,  c_m2_hi);
    cudaGetSymbolAddress((void**)&w_m2_l,  c_m2_lo);
    cudaGetSymbolAddress((void**)&w_out_h, c_out_hi);
    cudaGetSymbolAddress((void**)&w_out_l, c_out_lo);

    cudaFuncSetAttribute(k_attn, cudaFuncAttributeMaxDynamicSharedMemorySize, 49664);

    const int M = NB*NT;
    dim3 wblk(32, 8);

    // ---- weight conversion (every launch; deterministic) ----
    k_wconv<<<dim3((ND+31)/32,  (NMEL+31)/32), wblk>>>(W_in,  w_in_h,  w_in_l,  NMEL, ND);
    k_wconv<<<dim3((NMEL+31)/32,(ND+31)/32),   wblk>>>(W_out, w_out_h, w_out_l, ND, NMEL);
    for (int l = 0; l < NLAYER; l++){
        k_wconv<<<dim3(3*ND/32, ND/32), wblk>>>(qkv_W  + (size_t)l*ND*3*ND, w_qkv_h + (size_t)l*3*ND*ND, w_qkv_l + (size_t)l*3*ND*ND, ND, 3*ND);
        k_wconv<<<dim3(ND/32,   ND/32), wblk>>>(attno_W+ (size_t)l*ND*ND,   w_ao_h  + (size_t)l*ND*ND,   w_ao_l  + (size_t)l*ND*ND,   ND, ND);
        k_wconv<<<dim3(NFF/32,  ND/32), wblk>>>(mlp_W1 + (size_t)l*ND*NFF,  w_m1_h  + (size_t)l*NFF*ND,  w_m1_l  + (size_t)l*NFF*ND,  ND, NFF);
        k_wconv<<<dim3(ND/32,  NFF/32), wblk>>>(mlp_W2 + (size_t)l*NFF*ND,  w_m2_h  + (size_t)l*ND*NFF,  w_m2_l  + (size_t)l*ND*NFF,  NFF, ND);
    }

    // ---- timestep conditioning ----
    k_tfeat<<<(NB*NCD+255)/256,256>>>(t, p_ta);
    k_sgemm2<<<NCD/64,256>>>(p_ta, Wt1, bt1, p_tb, NCD, NCD, 1);
    k_sgemm2<<<NCD/64,256>>>(p_tb, Wt2, bt2, p_ta, NCD, NCD, 0);
    k_sgemm2<<<ND/64, 256>>>(p_ta, Wcm, bcm, p_cond, NCD, ND, 1);
    k_rope_tab<<<(NT*32+255)/256,256>>>();

    // input projection (K = 100)
    k_mgemm<<<dim3(8, 32), 256>>>(x, w_in_h, w_in_l, b_in, nullptr, p_h, ND, NMEL, 0);

    for (int l = 0; l < NLAYER; l++){
        k_sgemm2<<<2*ND/64,256>>>(p_cond, ada1_W + (size_t)l*ND*2*ND,
                                  ada1_b + (size_t)l*2*ND, p_ss, ND, 2*ND, 0);
        k_ln<<<M,256>>>(p_h, p_ss, p_hn);
        k_mgemm<<<dim3(24, 32), 256>>>(p_hn, w_qkv_h + (size_t)l*3*ND*ND,
                                       w_qkv_l + (size_t)l*3*ND*ND,
                                       qkv_b + (size_t)l*3*ND, nullptr, p_qkv,
                                       3*ND, ND, 0);
        k_rope<<<(1<<22)/256,256>>>(p_qkv);
        k_attn<<<dim3(NT/64, NH, NB), 256, 49664>>>(p_qkv, p_attn);
        k_mgemm<<<dim3(8, 32), 256>>>(p_attn, w_ao_h + (size_t)l*ND*ND,
                                      w_ao_l + (size_t)l*ND*ND,
                                      attno_b + (size_t)l*ND, p_h, p_h,
                                      ND, ND, 0);
        k_sgemm2<<<2*ND/64,256>>>(p_cond, ada2_W + (size_t)l*ND*2*ND,
                                  ada2_b + (size_t)l*2*ND, p_ss, ND, 2*ND, 0);
        k_ln<<<M,256>>>(p_h, p_ss, p_hn);
        k_mgemm<<<dim3(32, 32), 256>>>(p_hn, w_m1_h + (size_t)l*NFF*ND,
                                       w_m1_l + (size_t)l*NFF*ND,
                                       mlp_b1 + (size_t)l*NFF, nullptr, p_ff,
                                       NFF, ND, 1);
        k_mgemm<<<dim3(8, 32), 256>>>(p_ff, w_m2_h + (size_t)l*ND*NFF,
                                      w_m2_l + (size_t)l*ND*NFF,
                                      mlp_b2 + (size_t)l*ND, p_h, p_h,
                                      ND, NFF, 0);
    }

    k_ln<<<M,256>>>(p_h, nullptr, p_hn);
    k_mgemm<<<dim3(1, 32), 256>>>(p_hn, w_out_h, w_out_l, b_out, nullptr,
                                  (float*)d_out, NMEL, ND, 0);
}

// round 7
// speedup vs baseline: 2.3563x; 1.1536x over previous
#include <cuda_runtime.h>
#include <cuda_bf16.h>
#include <math.h>
#include <stdint.h>

#define NB   2
#define NT   2048
#define NMEL 100
#define ND   1024
#define NH   16
#define NDH  64
#define NWIN 512
#define NFF  4096
#define NCD  1024
#define NLAYER 6
#define LNEPS 1e-5f

// ---------------- scratch (device globals) ----------------
__device__ float g_h   [NB*NT*ND];
__device__ float g_qkv [NB*NT*3*ND];
__device__ float g_ta  [NB*NCD];
__device__ float g_tb  [NB*NCD];
__device__ float g_cond[NB*ND];
__device__ float g_ss  [NB*2*ND];
__device__ float g_rc  [NT*(NDH/2)];
__device__ float g_rs  [NT*(NDH/2)];

// split activations (bf16 hi/lo)
__device__ __nv_bfloat16 g_xh  [NB*NT*128];
__device__ __nv_bfloat16 g_xl  [NB*NT*128];
__device__ __nv_bfloat16 g_hn_h[NB*NT*ND];
__device__ __nv_bfloat16 g_hn_l[NB*NT*ND];
__device__ __nv_bfloat16 g_at_h[NB*NT*ND];
__device__ __nv_bfloat16 g_at_l[NB*NT*ND];
__device__ __nv_bfloat16 g_ff_h[NB*NT*NFF];
__device__ __nv_bfloat16 g_ff_l[NB*NT*NFF];

// converted weights: [N][Kpad] bf16 hi/lo
__device__ __nv_bfloat16 c_in_hi  [ND*128];        // K padded 100->128
__device__ __nv_bfloat16 c_in_lo  [ND*128];
__device__ __nv_bfloat16 c_qkv_hi [NLAYER*3*ND*ND];
__device__ __nv_bfloat16 c_qkv_lo [NLAYER*3*ND*ND];
__device__ __nv_bfloat16 c_ao_hi  [NLAYER*ND*ND];
__device__ __nv_bfloat16 c_ao_lo  [NLAYER*ND*ND];
__device__ __nv_bfloat16 c_m1_hi  [NLAYER*NFF*ND];
__device__ __nv_bfloat16 c_m1_lo  [NLAYER*NFF*ND];
__device__ __nv_bfloat16 c_m2_hi  [NLAYER*ND*NFF];
__device__ __nv_bfloat16 c_m2_lo  [NLAYER*ND*NFF];
__device__ __nv_bfloat16 c_out_hi [128*ND];        // N padded 100->128 rows
__device__ __nv_bfloat16 c_out_lo [128*ND];

// ---------------- helpers ----------------
__device__ __forceinline__ uint32_t smem_u32(const void* p){
    uint32_t a;
    asm("{ .reg .u64 t; cvta.to.shared.u64 t, %1; cvt.u32.u64 %0, t; }" : "=r"(a) : "l"(p));
    return a;
}
#define LDSM4(d0,d1,d2,d3,addr) \
    asm volatile("ldmatrix.sync.aligned.m8n8.x4.shared.b16 {%0,%1,%2,%3}, [%4];" \
        : "=r"(d0),"=r"(d1),"=r"(d2),"=r"(d3) : "r"(addr))
#define MMA16816(c, a, b0, b1) \
    asm volatile("mma.sync.aligned.m16n8k16.row.col.f32.bf16.bf16.f32 " \
        "{%0,%1,%2,%3},{%4,%5,%6,%7},{%8,%9},{%0,%1,%2,%3};" \
        : "+f"((c)[0]),"+f"((c)[1]),"+f"((c)[2]),"+f"((c)[3]) \
        : "r"((a)[0]),"r"((a)[1]),"r"((a)[2]),"r"((a)[3]),"r"(b0),"r"(b1))
#define CP_ASYNC16(dst, src) \
    asm volatile("cp.async.cg.shared.global [%0], [%1], 16;" :: "r"(dst), "l"(src))

__device__ __forceinline__ void split2(float v, __nv_bfloat16& h, __nv_bfloat16& l){
    h = __float2bfloat16_rn(v);
    l = __float2bfloat16_rn(v - __bfloat162float(h));
}

// ---------------- weight convert: W[K,N] fp32 -> [N,Kpad] bf16 hi/lo ----------------
__global__ void k_wconv(const float* __restrict__ W, __nv_bfloat16* __restrict__ hi,
                        __nv_bfloat16* __restrict__ lo, int K, int N, int Kpad){
    __shared__ float t[32][33];
    int kb = blockIdx.y*32, nb = blockIdx.x*32;
    int x = threadIdx.x, y = threadIdx.y;   // 32 x 8
    #pragma unroll
    for (int i = 0; i < 32; i += 8){
        int k = kb + y + i, n = nb + x;
        t[y+i][x] = (k < K && n < N) ? W[(size_t)k*N + n] : 0.f;
    }
    __syncthreads();
    #pragma unroll
    for (int i = 0; i < 32; i += 8){
        int n = nb + y + i, k = kb + x;
        if (n < N && k < Kpad){
            float v = t[x][y+i];
            __nv_bfloat16 h, l; split2(v, h, l);
            hi[(size_t)n*Kpad + k] = h;
            lo[(size_t)n*Kpad + k] = l;
        }
    }
}

// ---------------- x split: [M][K] fp32 -> [M][128] bf16 hi/lo (zero pad) ----------------
__global__ void k_split(const float* __restrict__ X, __nv_bfloat16* __restrict__ Xh,
                        __nv_bfloat16* __restrict__ Xl){
    int i = blockIdx.x*blockDim.x + threadIdx.x;   // M*128
    int row = i >> 7, col = i & 127;
    float v = (col < NMEL) ? X[(size_t)row*NMEL + col] : 0.f;
    __nv_bfloat16 h, l; split2(v, h, l);
    Xh[i] = h; Xl[i] = l;
}

// ---------------- pipelined tensor-core GEMM (bf16 hi/lo split, fp32 accum) ------------
// C = act(A @ B^T + bias) (+resid). A split [M][lda], B split [N][K]. K % 32 == 0.
#define SASTRIDE 40
#define TILE_ELEM (128*SASTRIDE)          // 5120 halves = 10240 B
#define STAGE_ELEM (4*TILE_ELEM)          // 20480 halves = 40960 B
__global__ __launch_bounds__(256, 2) void k_mgemm(
    const __nv_bfloat16* __restrict__ Ahi, const __nv_bfloat16* __restrict__ Alo, int lda,
    const __nv_bfloat16* __restrict__ Bhi, const __nv_bfloat16* __restrict__ Blo,
    const float* __restrict__ bias, const float* __restrict__ resid,
    float* __restrict__ C, __nv_bfloat16* __restrict__ Chi, __nv_bfloat16* __restrict__ Clo,
    int N, int K, int act)
{
    extern __shared__ __nv_bfloat16 sm[];   // 2 stages
    int tid = threadIdx.x, lane = tid & 31, w = tid >> 5;
    int m0 = blockIdx.y * 128, n0 = blockIdx.x * 128;
    int wm = (w & 1) * 64;
    int wn = (w >> 1) * 32;
    uint32_t sb = smem_u32(sm);

    float acc[16][4];
    #pragma unroll
    for (int i = 0; i < 16; i++){
        acc[i][0]=0.f; acc[i][1]=0.f; acc[i][2]=0.f; acc[i][3]=0.f;
    }

    int nchunks = K >> 5;

    // ---- prefetch helper ----
    #define PREFETCH(stage, k0) do {                                              \
        uint32_t s0 = sb + (stage)*(STAGE_ELEM*2);                                \
        _Pragma("unroll")                                                         \
        for (int j = 0; j < 8; j++){                                              \
            int i = tid + j*256;                                                  \
            int tile = i >> 9, r = (i >> 2) & 127, ch = i & 3;                    \
            const __nv_bfloat16* gp;                                              \
            if      (tile == 0) gp = Ahi + (size_t)(m0+r)*lda + (k0) + ch*8;      \
            else if (tile == 1) gp = Alo + (size_t)(m0+r)*lda + (k0) + ch*8;      \
            else if (tile == 2) gp = Bhi + (size_t)(n0+r)*K   + (k0) + ch*8;      \
            else                gp = Blo + (size_t)(n0+r)*K   + (k0) + ch*8;      \
            uint32_t dst = s0 + tile*(TILE_ELEM*2) + r*(SASTRIDE*2) + ch*16;      \
            CP_ASYNC16(dst, gp);                                                  \
        }                                                                         \
    } while(0)

    PREFETCH(0, 0);
    asm volatile("cp.async.commit_group;" ::: "memory");

    for (int c = 0; c < nchunks; c++){
        if (c + 1 < nchunks){
            PREFETCH((c+1)&1, (c+1)*32);
            asm volatile("cp.async.commit_group;" ::: "memory");
            asm volatile("cp.async.wait_group 1;" ::: "memory");
        } else {
            asm volatile("cp.async.wait_group 0;" ::: "memory");
        }
        __syncthreads();

        __nv_bfloat16* st  = sm + (c&1)*STAGE_ELEM;
        __nv_bfloat16* sAh = st;
        __nv_bfloat16* sAl = st + TILE_ELEM;
        __nv_bfloat16* sBh = st + 2*TILE_ELEM;
        __nv_bfloat16* sBl = st + 3*TILE_ELEM;

        #pragma unroll
        for (int ks = 0; ks < 2; ks++){
            int kb = ks * 16 + (lane >> 4) * 8;
            int rr = lane & 15;
            uint32_t ah[4][4], al[4][4], bfr[2][4];
            #pragma unroll
            for (int mi = 0; mi < 4; mi++){
                uint32_t ad = smem_u32(&sAh[(wm + mi*16 + rr)*SASTRIDE + kb]);
                LDSM4(ah[mi][0], ah[mi][1], ah[mi][2], ah[mi][3], ad);
            }
            #pragma unroll
            for (int mi = 0; mi < 4; mi++){
                uint32_t ad = smem_u32(&sAl[(wm + mi*16 + rr)*SASTRIDE + kb]);
                LDSM4(al[mi][0], al[mi][1], al[mi][2], al[mi][3], ad);
            }
            #pragma unroll
            for (int nj = 0; nj < 2; nj++){
                uint32_t ad = smem_u32(&sBh[(wn + nj*16 + rr)*SASTRIDE + kb]);
                LDSM4(bfr[nj][0], bfr[nj][1], bfr[nj][2], bfr[nj][3], ad);
            }
            #pragma unroll
            for (int mi = 0; mi < 4; mi++)
                #pragma unroll
                for (int ni = 0; ni < 4; ni++){
                    uint32_t b0 = bfr[ni>>1][(ni&1)];
                    uint32_t b1 = bfr[ni>>1][(ni&1)+2];
                    MMA16816(acc[mi*4+ni], ah[mi], b0, b1);   // hi*hi
                    MMA16816(acc[mi*4+ni], al[mi], b0, b1);   // lo*hi
                }
            #pragma unroll
            for (int nj = 0; nj < 2; nj++){
                uint32_t ad = smem_u32(&sBl[(wn + nj*16 + rr)*SASTRIDE + kb]);
                LDSM4(bfr[nj][0], bfr[nj][1], bfr[nj][2], bfr[nj][3], ad);
            }
            #pragma unroll
            for (int mi = 0; mi < 4; mi++)
                #pragma unroll
                for (int ni = 0; ni < 4; ni++){
                    uint32_t b0 = bfr[ni>>1][(ni&1)];
                    uint32_t b1 = bfr[ni>>1][(ni&1)+2];
                    MMA16816(acc[mi*4+ni], ah[mi], b0, b1);   // hi*lo
                }
        }
        __syncthreads();
    }

    // ---- epilogue ----
    #pragma unroll
    for (int mi = 0; mi < 4; mi++){
        #pragma unroll
        for (int ni = 0; ni < 4; ni++){
            float* ac = acc[mi*4+ni];
            int n = n0 + wn + ni*8 + (lane & 3)*2;
            if (n + 1 < N){
                float b0 = bias[n], b1 = bias[n+1];
                #pragma unroll
                for (int half = 0; half < 2; half++){
                    int m = m0 + wm + mi*16 + (lane >> 2) + half*8;
                    float v0 = ac[half*2]   + b0;
                    float v1 = ac[half*2+1] + b1;
                    if (act == 1){
                        v0 = 0.5f*v0*(1.f + erff(v0*0.70710678118654752f));
                        v1 = 0.5f*v1*(1.f + erff(v1*0.70710678118654752f));
                    }
                    if (Chi){
                        __nv_bfloat16 h0,l0,h1,l1;
                        split2(v0,h0,l0); split2(v1,h1,l1);
                        __nv_bfloat162 hp, lp;
                        hp.x=h0; hp.y=h1; lp.x=l0; lp.y=l1;
                        *(__nv_bfloat162*)(Chi + (size_t)m*N + n) = hp;
                        *(__nv_bfloat162*)(Clo + (size_t)m*N + n) = lp;
                    } else {
                        if (resid){
                            float2 rp = *(const float2*)(resid + (size_t)m*N + n);
                            v0 += rp.x; v1 += rp.y;
                        }
                        float2 o = make_float2(v0, v1);
                        *(float2*)(C + (size_t)m*N + n) = o;
                    }
                }
            } else if (n < N){
                float b0 = bias[n];
                #pragma unroll
                for (int half = 0; half < 2; half++){
                    int m = m0 + wm + mi*16 + (lane >> 2) + half*8;
                    float v0 = ac[half*2] + b0;
                    if (act == 1) v0 = 0.5f*v0*(1.f + erff(v0*0.70710678118654752f));
                    if (Chi){
                        __nv_bfloat16 h0,l0; split2(v0,h0,l0);
                        Chi[(size_t)m*N + n] = h0;
                        Clo[(size_t)m*N + n] = l0;
                    } else {
                        if (resid) v0 += resid[(size_t)m*N + n];
                        C[(size_t)m*N + n] = v0;
                    }
                }
            }
        }
    }
    #undef PREFETCH
}

// ---------------- timestep embedding features ----------------
__global__ void k_tfeat(const float* __restrict__ t, float* __restrict__ out){
    int i = blockIdx.x*blockDim.x + threadIdx.x;
    if (i >= NB*NCD) return;
    int b = i / NCD, j = i % NCD;
    const int half = NCD/2;
    int idx = (j < half) ? j : (j - half);
    float f   = expf(-9.210340371976184f * (float)idx / (float)half);
    float ang = t[b] * f;
    out[i] = (j < half) ? sinf(ang) : cosf(ang);
}

// ---------------- small GEMM (rows = NB only), k-split parallel ----------------
__global__ __launch_bounds__(256) void k_sgemm2(const float* __restrict__ X,
                                                const float* __restrict__ W,
                                                const float* __restrict__ bias,
                                                float* __restrict__ Y,
                                                int K, int N, int act){
    __shared__ float red[2][4][65];
    int lane = threadIdx.x & 63;
    int slice = threadIdx.x >> 6;
    int n = blockIdx.x*64 + lane;
    int kps = K >> 2;
    float a0 = 0.f, a1 = 0.f;
    if (n < N){
        const float* x0 = X;
        const float* x1 = X + K;
        int k0 = slice*kps, k1 = k0 + kps;
        #pragma unroll 4
        for (int k = k0; k < k1; k++){
            float w = W[(size_t)k*N + n];
            a0 += x0[k]*w; a1 += x1[k]*w;
        }
    }
    red[0][slice][lane] = a0;
    red[1][slice][lane] = a1;
    __syncthreads();
    if (threadIdx.x < 128){
        int bb = threadIdx.x >> 6, l = threadIdx.x & 63;
        float s = red[bb][0][l] + red[bb][1][l] + red[bb][2][l] + red[bb][3][l];
        int nn = blockIdx.x*64 + l;
        if (nn < N){
            s += bias[nn];
            if (act == 1) s = s / (1.f + expf(-s));
            Y[(size_t)bb*N + nn] = s;
        }
    }
}

// ---------------- rope tables + apply ----------------
__global__ void k_rope_tab(){
    int i = blockIdx.x*blockDim.x + threadIdx.x;
    if (i >= NT*(NDH/2)) return;
    int t = i >> 5, j = i & 31;
    float freq = (float)pow(10000.0, -(double)(2*j) / (double)NDH);
    float ang  = (float)t * freq;
    g_rc[i] = cosf(ang);
    g_rs[i] = sinf(ang);
}
__global__ void k_rope(float* __restrict__ qkv){
    int i = blockIdx.x*blockDim.x + threadIdx.x;
    int j = i & 31;
    int h = (i >> 5) & 15;
    int c = (i >> 9) & 1;
    int t = (i >> 10) & (NT-1);
    int b = i >> 21;
    size_t base = (((size_t)(b*NT + t)*3 + c)*NH + h) * NDH;
    float x1 = qkv[base + 2*j], x2 = qkv[base + 2*j + 1];
    float cs = g_rc[t*32 + j], sn = g_rs[t*32 + j];
    qkv[base + 2*j]     = x1*cs - x2*sn;
    qkv[base + 2*j + 1] = x1*sn + x2*cs;
}

// ---------------- LayerNorm (+adaLN), split bf16 hi/lo output ----------------
__global__ __launch_bounds__(256) void k_ln(const float* __restrict__ X,
                                            const float* __restrict__ ss,
                                            __nv_bfloat16* __restrict__ Yh,
                                            __nv_bfloat16* __restrict__ Yl){
    int row = blockIdx.x;
    int b = row / NT;
    const float4* x4 = (const float4*)(X + (size_t)row*ND);
    int tid = threadIdx.x;
    float4 v = x4[tid];
    float s = v.x+v.y+v.z+v.w;
    float q = v.x*v.x+v.y*v.y+v.z*v.z+v.w*v.w;
    #pragma unroll
    for (int o=16;o;o>>=1){ s += __shfl_xor_sync(0xffffffffu,s,o); q += __shfl_xor_sync(0xffffffffu,q,o); }
    __shared__ float shs[8], shq[8];
    __shared__ float smean, srstd;
    int w = tid>>5;
    if ((tid&31)==0){ shs[w]=s; shq[w]=q; }
    __syncthreads();
    if (tid==0){
        float S=0.f,Q=0.f;
        #pragma unroll
        for (int k=0;k<8;k++){ S+=shs[k]; Q+=shq[k]; }
        float mean = S*(1.f/ND);
        float var  = Q*(1.f/ND) - mean*mean;
        smean = mean; srstd = rsqrtf(var + LNEPS);
    }
    __syncthreads();
    float mean = smean, r = srstd;
    int n0 = tid*4;
    float o[4];
    o[0]=(v.x-mean)*r; o[1]=(v.y-mean)*r; o[2]=(v.z-mean)*r; o[3]=(v.w-mean)*r;
    if (ss){
        const float* sc = ss + (size_t)b*2*ND;
        const float* sh = sc + ND;
        #pragma unroll
        for (int j=0;j<4;j++) o[j] = o[j]*(1.f+sc[n0+j]) + sh[n0+j];
    }
    __nv_bfloat16 hh[4], ll[4];
    #pragma unroll
    for (int j=0;j<4;j++) split2(o[j], hh[j], ll[j]);
    *(uint2*)(Yh + (size_t)row*ND + n0) = *(uint2*)hh;
    *(uint2*)(Yl + (size_t)row*ND + n0) = *(uint2*)ll;
}

// ---------------- flash-style windowed causal attention (fp32, split bf16 out) --------
__global__ __launch_bounds__(256) void k_attn(const float* __restrict__ qkv,
                                              __nv_bfloat16* __restrict__ Oh,
                                              __nv_bfloat16* __restrict__ Ol){
    extern __shared__ float smf[];
    float* Qs = smf;
    float* KP = smf + 64*65;
    float* Vs = smf + 2*64*65;
    int qt = blockIdx.x, h = blockIdx.y, b = blockIdx.z;
    int tid = threadIdx.x, ty = tid>>4, tx = tid&15;
    int q0 = qt*64;
    const float scale = 0.125f;

    #pragma unroll
    for (int rep=0;rep<4;rep++){
        int f = tid + rep*256;
        int r = f>>4, c4 = (f&15)*4;
        size_t g = (((size_t)(b*NT + q0 + r)*3 + 0)*NH + h)*NDH + c4;
        float4 v = *(const float4*)(qkv + g);
        Qs[r*65 + c4  ] = v.x*scale;
        Qs[r*65 + c4+1] = v.y*scale;
        Qs[r*65 + c4+2] = v.z*scale;
        Qs[r*65 + c4+3] = v.w*scale;
    }
    __syncthreads();

    float Oa[4][4];
    float mo[4], lo[4];
    #pragma unroll
    for (int a=0;a<4;a++){
        mo[a] = -1e30f; lo[a] = 0.f;
        #pragma unroll
        for (int c=0;c<4;c++) Oa[a][c]=0.f;
    }

    int ktiles = min(8, qt+1);
    for (int jt=0; jt<ktiles; jt++){
        int j0 = jt*64;
        #pragma unroll
        for (int rep=0;rep<4;rep++){
            int f = tid + rep*256;
            int r = f>>4, c4 = (f&15)*4;
            int tok = NT - NWIN + j0 + r;
            size_t gk = (((size_t)(b*NT + tok)*3 + 1)*NH + h)*NDH + c4;
            float4 kv = *(const float4*)(qkv + gk);
            float4 vv = *(const float4*)(qkv + gk + (size_t)NH*NDH);
            KP[r*65+c4  ]=kv.x; KP[r*65+c4+1]=kv.y;
            KP[r*65+c4+2]=kv.z; KP[r*65+c4+3]=kv.w;
            *(float4*)(Vs + r*64 + c4) = vv;
        }
        __syncthreads();

        float S[4][4];
        #pragma unroll
        for (int a=0;a<4;a++)
            #pragma unroll
            for (int bb=0;bb<4;bb++) S[a][bb]=0.f;
        for (int d=0; d<64; d++){
            float qa[4], kb[4];
            #pragma unroll
            for (int a=0;a<4;a++)  qa[a] = Qs[(ty+16*a)*65 + d];
            #pragma unroll
            for (int bb=0;bb<4;bb++) kb[bb] = KP[(tx+16*bb)*65 + d];
            #pragma unroll
            for (int a=0;a<4;a++)
                #pragma unroll
                for (int bb=0;bb<4;bb++) S[a][bb] += qa[a]*kb[bb];
        }
        if (jt == qt){
            #pragma unroll
            for (int a=0;a<4;a++)
                #pragma unroll
                for (int bb=0;bb<4;bb++)
                    if (tx+16*bb > ty+16*a) S[a][bb] = -1e30f;
        }

        float P[4][4];
        #pragma unroll
        for (int a=0;a<4;a++){
            float mx = fmaxf(fmaxf(S[a][0],S[a][1]), fmaxf(S[a][2],S[a][3]));
            mx = fmaxf(mx, __shfl_xor_sync(0xffffffffu, mx, 8));
            mx = fmaxf(mx, __shfl_xor_sync(0xffffffffu, mx, 4));
            mx = fmaxf(mx, __shfl_xor_sync(0xffffffffu, mx, 2));
            mx = fmaxf(mx, __shfl_xor_sync(0xffffffffu, mx, 1));
            float mn = fmaxf(mo[a], mx);
            float ls = 0.f;
            #pragma unroll
            for (int bb=0;bb<4;bb++){ P[a][bb] = expf(S[a][bb]-mn); ls += P[a][bb]; }
            ls += __shfl_xor_sync(0xffffffffu, ls, 8);
            ls += __shfl_xor_sync(0xffffffffu, ls, 4);
            ls += __shfl_xor_sync(0xffffffffu, ls, 2);
            ls += __shfl_xor_sync(0xffffffffu, ls, 1);
            float alpha = expf(mo[a]-mn);
            lo[a] = lo[a]*alpha + ls;
            mo[a] = mn;
            #pragma unroll
            for (int c=0;c<4;c++) Oa[a][c] *= alpha;
        }
        __syncthreads();
        #pragma unroll
        for (int a=0;a<4;a++)
            #pragma unroll
            for (int bb=0;bb<4;bb++)
                KP[(ty+16*a)*65 + tx+16*bb] = P[a][bb];
        __syncthreads();
        for (int jj=0;jj<64;jj++){
            float pa[4], vc[4];
            #pragma unroll
            for (int a=0;a<4;a++) pa[a] = KP[(ty+16*a)*65 + jj];
            #pragma unroll
            for (int c=0;c<4;c++) vc[c] = Vs[jj*64 + tx+16*c];
            #pragma unroll
            for (int a=0;a<4;a++)
                #pragma unroll
                for (int c=0;c<4;c++) Oa[a][c] += pa[a]*vc[c];
        }
        __syncthreads();
    }
    #pragma unroll
    for (int a=0;a<4;a++){
        int qq = q0 + ty + 16*a;
        float inv = 1.f/lo[a];
        #pragma unroll
        for (int c=0;c<4;c++){
            float v = Oa[a][c]*inv;
            __nv_bfloat16 hh, ll; split2(v, hh, ll);
            size_t idx = (((size_t)(b*NT+qq))*NH + h)*NDH + tx + 16*c;
            Oh[idx] = hh; Ol[idx] = ll;
        }
    }
}

// ---------------- orchestration ----------------
extern "C" void kernel_launch(void* const* d_in, const int* in_sizes, int n_in,
                              void* d_out, int out_size){
    (void)in_sizes; (void)n_in; (void)out_size;
    const float* x      = (const float*)d_in[0];
    const float* t      = (const float*)d_in[1];
    const float* W_in   = (const float*)d_in[2];
    const float* b_in   = (const float*)d_in[3];
    const float* Wt1    = (const float*)d_in[4];
    const float* bt1    = (const float*)d_in[5];
    const float* Wt2    = (const float*)d_in[6];
    const float* bt2    = (const float*)d_in[7];
    const float* Wcm    = (const float*)d_in[8];
    const float* bcm    = (const float*)d_in[9];
    const float* ada1_W = (const float*)d_in[10];
    const float* ada1_b = (const float*)d_in[11];
    const float* qkv_W  = (const float*)d_in[12];
    const float* qkv_b  = (const float*)d_in[13];
    const float* attno_W= (const float*)d_in[14];
    const float* attno_b= (const float*)d_in[15];
    const float* ada2_W = (const float*)d_in[16];
    const float* ada2_b = (const float*)d_in[17];
    const float* mlp_W1 = (const float*)d_in[18];
    const float* mlp_b1 = (const float*)d_in[19];
    const float* mlp_W2 = (const float*)d_in[20];
    const float* mlp_b2 = (const float*)d_in[21];
    const float* W_out  = (const float*)d_in[22];
    const float* b_out  = (const float*)d_in[23];

    float *p_h,*p_qkv,*p_ta,*p_tb,*p_cond,*p_ss;
    cudaGetSymbolAddress((void**)&p_h,    g_h);
    cudaGetSymbolAddress((void**)&p_qkv,  g_qkv);
    cudaGetSymbolAddress((void**)&p_ta,   g_ta);
    cudaGetSymbolAddress((void**)&p_tb,   g_tb);
    cudaGetSymbolAddress((void**)&p_cond, g_cond);
    cudaGetSymbolAddress((void**)&p_ss,   g_ss);

    __nv_bfloat16 *p_xh,*p_xl,*p_hnh,*p_hnl,*p_ath,*p_atl,*p_ffh,*p_ffl;
    cudaGetSymbolAddress((void**)&p_xh,  g_xh);
    cudaGetSymbolAddress((void**)&p_xl,  g_xl);
    cudaGetSymbolAddress((void**)&p_hnh, g_hn_h);
    cudaGetSymbolAddress((void**)&p_hnl, g_hn_l);
    cudaGetSymbolAddress((void**)&p_ath, g_at_h);
    cudaGetSymbolAddress((void**)&p_atl, g_at_l);
    cudaGetSymbolAddress((void**)&p_ffh, g_ff_h);
    cudaGetSymbolAddress((void**)&p_ffl, g_ff_l);

    __nv_bfloat16 *w_in_h,*w_in_l,*w_qkv_h,*w_qkv_l,*w_ao_h,*w_ao_l;
    __nv_bfloat16 *w_m1_h,*w_m1_l,*w_m2_h,*w_m2_l,*w_out_h,*w_out_l;
    cudaGetSymbolAddress((void**)&w_in_h,  c_in_hi);
    cudaGetSymbolAddress((void**)&w_in_l,  c_in_lo);
    cudaGetSymbolAddress((void**)&w_qkv_h, c_qkv_hi);
    cudaGetSymbolAddress((void**)&w_qkv_l, c_qkv_lo);
    cudaGetSymbolAddress((void**)&w_ao_h,  c_ao_hi);
    cudaGetSymbolAddress((void**)&w_ao_l,  c_ao_lo);
    cudaGetSymbolAddress((void**)&w_m1_h,  c_m1_hi);
    cudaGetSymbolAddress((void**)&w_m1_l,  c_m1_lo);
    cudaGetSymbolAddress((void**)&w_m2_h,  c_m2_hi);
    cudaGetSymbolAddress((void**)&w_m2_l,  c_m2_lo);
    cudaGetSymbolAddress((void**)&w_out_h, c_out_hi);
    cudaGetSymbolAddress((void**)&w_out_l, c_out_lo);

    cudaFuncSetAttribute(k_attn,  cudaFuncAttributeMaxDynamicSharedMemorySize, 49664);
    cudaFuncSetAttribute(k_mgemm, cudaFuncAttributeMaxDynamicSharedMemorySize, 81920);

    const int M = NB*NT;
    const int MG_SMEM = 81920;
    dim3 wblk(32, 8);

    // ---- weight conversion ----
    k_wconv<<<dim3(ND/32, 128/32), wblk>>>(W_in,  w_in_h,  w_in_l,  NMEL, ND, 128);
    k_wconv<<<dim3((NMEL+31)/32, ND/32), wblk>>>(W_out, w_out_h, w_out_l, ND, NMEL, ND);
    for (int l = 0; l < NLAYER; l++){
        k_wconv<<<dim3(3*ND/32, ND/32), wblk>>>(qkv_W  + (size_t)l*ND*3*ND, w_qkv_h + (size_t)l*3*ND*ND, w_qkv_l + (size_t)l*3*ND*ND, ND, 3*ND, ND);
        k_wconv<<<dim3(ND/32,   ND/32), wblk>>>(attno_W+ (size_t)l*ND*ND,   w_ao_h  + (size_t)l*ND*ND,   w_ao_l  + (size_t)l*ND*ND,   ND, ND, ND);
        k_wconv<<<dim3(NFF/32,  ND/32), wblk>>>(mlp_W1 + (size_t)l*ND*NFF,  w_m1_h  + (size_t)l*NFF*ND,  w_m1_l  + (size_t)l*NFF*ND,  ND, NFF, ND);
        k_wconv<<<dim3(ND/32,  NFF/32), wblk>>>(mlp_W2 + (size_t)l*NFF*ND,  w_m2_h  + (size_t)l*ND*NFF,  w_m2_l  + (size_t)l*ND*NFF,  NFF, ND, NFF);
    }

    // ---- timestep conditioning ----
    k_tfeat<<<(NB*NCD+255)/256,256>>>(t, p_ta);
    k_sgemm2<<<NCD/64,256>>>(p_ta, Wt1, bt1, p_tb, NCD, NCD, 1);
    k_sgemm2<<<NCD/64,256>>>(p_tb, Wt2, bt2, p_ta, NCD, NCD, 0);
    k_sgemm2<<<ND/64, 256>>>(p_ta, Wcm, bcm, p_cond, NCD, ND, 1);
    k_rope_tab<<<(NT*32+255)/256,256>>>();

    // ---- input projection (padded K = 128) ----
    k_split<<<(M*128)/256, 256>>>(x, p_xh, p_xl);
    k_mgemm<<<dim3(8, 32), 256, MG_SMEM>>>(p_xh, p_xl, 128, w_in_h, w_in_l,
                                           b_in, nullptr, p_h, nullptr, nullptr,
                                           ND, 128, 0);

    for (int l = 0; l < NLAYER; l++){
        k_sgemm2<<<2*ND/64,256>>>(p_cond, ada1_W + (size_t)l*ND*2*ND,
                                  ada1_b + (size_t)l*2*ND, p_ss, ND, 2*ND, 0);
        k_ln<<<M,256>>>(p_h, p_ss, p_hnh, p_hnl);
        k_mgemm<<<dim3(24, 32), 256, MG_SMEM>>>(p_hnh, p_hnl, ND,
                                                w_qkv_h + (size_t)l*3*ND*ND,
                                                w_qkv_l + (size_t)l*3*ND*ND,
                                                qkv_b + (size_t)l*3*ND, nullptr,
                                                p_qkv, nullptr, nullptr,
                                                3*ND, ND, 0);
        k_rope<<<(1<<22)/256,256>>>(p_qkv);
        k_attn<<<dim3(NT/64, NH, NB), 256, 49664>>>(p_qkv, p_ath, p_atl);
        k_mgemm<<<dim3(8, 32), 256, MG_SMEM>>>(p_ath, p_atl, ND,
                                               w_ao_h + (size_t)l*ND*ND,
                                               w_ao_l + (size_t)l*ND*ND,
                                               attno_b + (size_t)l*ND, p_h,
                                               p_h, nullptr, nullptr,
                                               ND, ND, 0);
        k_sgemm2<<<2*ND/64,256>>>(p_cond, ada2_W + (size_t)l*ND*2*ND,
                                  ada2_b + (size_t)l*2*ND, p_ss, ND, 2*ND, 0);
        k_ln<<<M,256>>>(p_h, p_ss, p_hnh, p_hnl);
        k_mgemm<<<dim3(32, 32), 256, MG_SMEM>>>(p_hnh, p_hnl, ND,
                                                w_m1_h + (size_t)l*NFF*ND,
                                                w_m1_l + (size_t)l*NFF*ND,
                                                mlp_b1 + (size_t)l*NFF, nullptr,
                                                nullptr, p_ffh, p_ffl,
                                                NFF, ND, 1);
        k_mgemm<<<dim3(8, 32), 256, MG_SMEM>>>(p_ffh, p_ffl, NFF,
                                               w_m2_h + (size_t)l*ND*NFF,
                                               w_m2_l + (size_t)l*ND*NFF,
                                               mlp_b2 + (size_t)l*ND, p_h,
                                               p_h, nullptr, nullptr,
                                               ND, NFF, 0);
    }

    k_ln<<<M,256>>>(p_h, nullptr, p_hnh, p_hnl);
    k_mgemm<<<dim3(1, 32), 256, MG_SMEM>>>(p_hnh, p_hnl, ND, w_out_h, w_out_l,
                                           b_out, nullptr, (float*)d_out,
                                           nullptr, nullptr, NMEL, ND, 0);
}